// round 1
// baseline (speedup 1.0000x reference)
#include <cuda_runtime.h>
#include <cuda_bf16.h>
#include <math.h>

// Problem dims (fixed by reference)
#define NB 4
#define SEQ 2048
#define EMB 1024
#define NH 16
#define HD 64
#define FF 4096
#define MROWS (NB * SEQ)          // 8192
#define X_SIZE (NB * SEQ * EMB)   // 8388608

// ---------------- scratch (device globals; no allocation allowed) ----------
__device__ float g_xn [MROWS * EMB];
__device__ float g_q  [MROWS * EMB];
__device__ float g_k  [MROWS * EMB];
__device__ float g_v  [MROWS * EMB];
__device__ float g_att[MROWS * EMB];
__device__ float g_x1 [MROWS * EMB];
__device__ float g_xn2[MROWS * EMB];
__device__ float g_ffn[MROWS * FF];

// ---------------- layernorm: one block per row of 1024 ---------------------
__global__ __launch_bounds__(256) void ln_kernel(
    const float* __restrict__ in, const float* __restrict__ g,
    const float* __restrict__ b, float* __restrict__ out)
{
    const int row = blockIdx.x;
    const float* xr = in + (size_t)row * EMB;
    float* orow = out + (size_t)row * EMB;
    const int tid = threadIdx.x;

    float vals[4];
    float s = 0.f, sq = 0.f;
#pragma unroll
    for (int i = 0; i < 4; i++) {
        float v = xr[i * 256 + tid];
        vals[i] = v; s += v; sq += v * v;
    }
    // block reduce (sum, sumsq)
    __shared__ float red[16];
#pragma unroll
    for (int off = 16; off; off >>= 1) {
        s  += __shfl_xor_sync(0xffffffffu, s,  off);
        sq += __shfl_xor_sync(0xffffffffu, sq, off);
    }
    const int warp = tid >> 5, lane = tid & 31;
    if (lane == 0) { red[warp] = s; red[warp + 8] = sq; }
    __syncthreads();
    if (warp == 0) {
        float ss = (lane < 8) ? red[lane] : 0.f;
        float qq = (lane < 8) ? red[lane + 8] : 0.f;
#pragma unroll
        for (int off = 4; off; off >>= 1) {
            ss += __shfl_xor_sync(0xffffffffu, ss, off);
            qq += __shfl_xor_sync(0xffffffffu, qq, off);
        }
        if (lane == 0) { red[0] = ss; red[1] = qq; }
    }
    __syncthreads();
    const float mean = red[0] * (1.0f / EMB);
    const float var  = red[1] * (1.0f / EMB) - mean * mean;
    const float inv  = rsqrtf(var + 1e-5f);
#pragma unroll
    for (int i = 0; i < 4; i++) {
        int idx = i * 256 + tid;
        orow[idx] = (vals[i] - mean) * inv * g[idx] + b[idx];
    }
}

// ---------------- SGEMM: C = act(A@B + bias [+ res]) -----------------------
// A [M,K] rm, B [K,N] rm, bias [N], res [M,N], C [M,N].
// 128x128 tile, BK=8, 256 threads, 8x8 per thread.
template <bool RELU, bool RES>
__global__ __launch_bounds__(256) void gemm_kernel(
    const float* __restrict__ A, const float* __restrict__ B,
    const float* __restrict__ bias, const float* __restrict__ res,
    float* __restrict__ C, int M, int N, int K)
{
    __shared__ float As[8][128];
    __shared__ float Bs[8][128];

    const int tid = threadIdx.x;
    const int ty = tid >> 4, tx = tid & 15;
    const int rowStart = blockIdx.y * 128;
    const int colStart = blockIdx.x * 128;

    const int aRow = tid >> 1, aCol = (tid & 1) * 4;
    const int bRow = tid >> 5, bCol = (tid & 31) * 4;

    float acc[8][8];
#pragma unroll
    for (int i = 0; i < 8; i++)
#pragma unroll
        for (int j = 0; j < 8; j++) acc[i][j] = 0.f;

    for (int k0 = 0; k0 < K; k0 += 8) {
        float4 av = *reinterpret_cast<const float4*>(
            &A[(size_t)(rowStart + aRow) * K + k0 + aCol]);
        As[aCol + 0][aRow] = av.x;
        As[aCol + 1][aRow] = av.y;
        As[aCol + 2][aRow] = av.z;
        As[aCol + 3][aRow] = av.w;
        float4 bv = *reinterpret_cast<const float4*>(
            &B[(size_t)(k0 + bRow) * N + colStart + bCol]);
        *reinterpret_cast<float4*>(&Bs[bRow][bCol]) = bv;
        __syncthreads();

#pragma unroll
        for (int k = 0; k < 8; k++) {
            float4 a0 = *reinterpret_cast<const float4*>(&As[k][ty * 8]);
            float4 a1 = *reinterpret_cast<const float4*>(&As[k][ty * 8 + 4]);
            float4 b0 = *reinterpret_cast<const float4*>(&Bs[k][tx * 8]);
            float4 b1 = *reinterpret_cast<const float4*>(&Bs[k][tx * 8 + 4]);
            float a[8] = {a0.x, a0.y, a0.z, a0.w, a1.x, a1.y, a1.z, a1.w};
            float b[8] = {b0.x, b0.y, b0.z, b0.w, b1.x, b1.y, b1.z, b1.w};
#pragma unroll
            for (int i = 0; i < 8; i++)
#pragma unroll
                for (int j = 0; j < 8; j++)
                    acc[i][j] = fmaf(a[i], b[j], acc[i][j]);
        }
        __syncthreads();
    }

#pragma unroll
    for (int i = 0; i < 8; i++) {
        const int row = rowStart + ty * 8 + i;
#pragma unroll
        for (int j = 0; j < 8; j++) {
            const int col = colStart + tx * 8 + j;
            float r = acc[i][j] + bias[col];
            if (RES) r += res[(size_t)row * N + col];
            if (RELU) r = fmaxf(r, 0.f);
            C[(size_t)row * N + col] = r;
        }
    }
}

// ---------------- flash attention (fp32) ------------------------------------
// q,k,v,out: [NB, SEQ, EMB] with head h occupying cols h*64..h*64+63.
// grid: (SEQ/64, NH, NB); 256 threads; Q-tile 64, K-tile 32.
__global__ __launch_bounds__(256) void attn_kernel(
    const float* __restrict__ q, const float* __restrict__ k,
    const float* __restrict__ v, float* __restrict__ out)
{
    __shared__ float Qs[64][HD + 1];
    __shared__ float Ks[32][HD + 1];
    __shared__ float Vs[32][HD + 1];
    __shared__ float Ps[64][33];

    const int qt = blockIdx.x, h = blockIdx.y, n = blockIdx.z;
    const int tid = threadIdx.x;
    const int r = tid >> 2;      // query row within tile (0..63)
    const int c4 = tid & 3;      // quarter index
    const float scale = 0.125f;  // 1/sqrt(64)

    const size_t base = ((size_t)n * SEQ) * EMB + h * HD;

    for (int i = tid; i < 64 * HD; i += 256) {
        int rr = i >> 6, d = i & 63;
        Qs[rr][d] = q[base + (size_t)(qt * 64 + rr) * EMB + d] * scale;
    }

    float m = -INFINITY, l = 0.f;
    float o[16];
#pragma unroll
    for (int i = 0; i < 16; i++) o[i] = 0.f;
    const int d0 = c4 * 16;
    const int c0 = c4 * 8;

    for (int kt = 0; kt < SEQ / 32; kt++) {
        __syncthreads();  // previous iter done reading Ks/Vs/Ps
        for (int i = tid; i < 32 * HD; i += 256) {
            int rr = i >> 6, d = i & 63;
            size_t gi = base + (size_t)(kt * 32 + rr) * EMB + d;
            Ks[rr][d] = k[gi];
            Vs[rr][d] = v[gi];
        }
        __syncthreads();

        float s[8];
#pragma unroll
        for (int j = 0; j < 8; j++) s[j] = 0.f;
        for (int d = 0; d < HD; d++) {
            float qv = Qs[r][d];
#pragma unroll
            for (int j = 0; j < 8; j++)
                s[j] = fmaf(qv, Ks[c0 + j][d], s[j]);
        }
        float mt = s[0];
#pragma unroll
        for (int j = 1; j < 8; j++) mt = fmaxf(mt, s[j]);
        mt = fmaxf(mt, __shfl_xor_sync(0xffffffffu, mt, 1));
        mt = fmaxf(mt, __shfl_xor_sync(0xffffffffu, mt, 2));

        const float mn = fmaxf(m, mt);
        const float corr = __expf(m - mn);
        float ls = 0.f;
#pragma unroll
        for (int j = 0; j < 8; j++) {
            float p = __expf(s[j] - mn);
            Ps[r][c0 + j] = p;
            ls += p;
        }
        ls += __shfl_xor_sync(0xffffffffu, ls, 1);
        ls += __shfl_xor_sync(0xffffffffu, ls, 2);
        l = l * corr + ls;
        m = mn;
#pragma unroll
        for (int i = 0; i < 16; i++) o[i] *= corr;
        __syncthreads();  // Ps visible to whole row

        for (int j = 0; j < 32; j++) {
            float pv = Ps[r][j];
#pragma unroll
            for (int dd = 0; dd < 16; dd++)
                o[dd] = fmaf(pv, Vs[j][d0 + dd], o[dd]);
        }
    }

    const float invl = 1.f / l;
    const size_t ob = base + (size_t)(qt * 64 + r) * EMB + d0;
#pragma unroll
    for (int dd = 0; dd < 16; dd++) out[ob + dd] = o[dd] * invl;
}

// ---------------- logits + GAN loss -----------------------------------------
__global__ void loss_kernel(const float* __restrict__ xfin,
                            const float* __restrict__ wlr,
                            const float* __restrict__ blr,
                            float* __restrict__ out)  // out -> d_out + X_SIZE
{
    __shared__ float slog[4];
    const int warp = threadIdx.x >> 5, lane = threadIdx.x & 31;
    if (warp < 4) {
        const float* xr = xfin + (size_t)warp * SEQ * EMB;  // token 0
        float s = 0.f;
        for (int i = lane; i < EMB; i += 32) s = fmaf(xr[i], wlr[i], s);
#pragma unroll
        for (int off = 16; off; off >>= 1)
            s += __shfl_xor_sync(0xffffffffu, s, off);
        if (lane == 0) slog[warp] = s + blr[0];
    }
    __syncthreads();
    if (threadIdx.x == 0) {
        auto sp = [](float t) {
            return fmaxf(t, 0.f) + log1pf(expf(-fabsf(t)));
        };
        float loss_real = 0.5f * (sp(-slog[0]) + sp(-slog[1]));
        float loss_fake = 0.5f * (sp( slog[2]) + sp( slog[3]));
        out[0] = 0.5f * (loss_fake + loss_real);
        out[1] = loss_fake;
    }
}

// ---------------- launch ----------------------------------------------------
extern "C" void kernel_launch(void* const* d_in, const int* in_sizes, int n_in,
                              void* d_out, int out_size)
{
    const float* x     = (const float*)d_in[0];
    const float* wq    = (const float*)d_in[1];
    const float* bq    = (const float*)d_in[2];
    const float* wk    = (const float*)d_in[3];
    const float* bk    = (const float*)d_in[4];
    const float* wv    = (const float*)d_in[5];
    const float* bv    = (const float*)d_in[6];
    const float* wo    = (const float*)d_in[7];
    const float* bo    = (const float*)d_in[8];
    const float* ln1_g = (const float*)d_in[9];
    const float* ln1_b = (const float*)d_in[10];
    const float* ln2_g = (const float*)d_in[11];
    const float* ln2_b = (const float*)d_in[12];
    const float* w1    = (const float*)d_in[13];
    const float* b1    = (const float*)d_in[14];
    const float* w2    = (const float*)d_in[15];
    const float* b2    = (const float*)d_in[16];
    const float* wlr   = (const float*)d_in[17];
    const float* blr   = (const float*)d_in[18];
    float* out = (float*)d_out;

    float *xn, *q, *k, *v, *att, *x1, *xn2, *ffn;
    cudaGetSymbolAddress((void**)&xn,  g_xn);
    cudaGetSymbolAddress((void**)&q,   g_q);
    cudaGetSymbolAddress((void**)&k,   g_k);
    cudaGetSymbolAddress((void**)&v,   g_v);
    cudaGetSymbolAddress((void**)&att, g_att);
    cudaGetSymbolAddress((void**)&x1,  g_x1);
    cudaGetSymbolAddress((void**)&xn2, g_xn2);
    cudaGetSymbolAddress((void**)&ffn, g_ffn);

    // 1) LN1
    ln_kernel<<<MROWS, 256>>>(x, ln1_g, ln1_b, xn);

    // 2) Q,K,V projections
    dim3 gProj(EMB / 128, MROWS / 128);
    gemm_kernel<false, false><<<gProj, 256>>>(xn, wq, bq, nullptr, q, MROWS, EMB, EMB);
    gemm_kernel<false, false><<<gProj, 256>>>(xn, wk, bk, nullptr, k, MROWS, EMB, EMB);
    gemm_kernel<false, false><<<gProj, 256>>>(xn, wv, bv, nullptr, v, MROWS, EMB, EMB);

    // 3) attention
    dim3 gAttn(SEQ / 64, NH, NB);
    attn_kernel<<<gAttn, 256>>>(q, k, v, att);

    // 4) out-proj + residual -> x1
    gemm_kernel<false, true><<<gProj, 256>>>(att, wo, bo, x, x1, MROWS, EMB, EMB);

    // 5) LN2
    ln_kernel<<<MROWS, 256>>>(x1, ln2_g, ln2_b, xn2);

    // 6) FFN1 with ReLU
    dim3 gFF1(FF / 128, MROWS / 128);
    gemm_kernel<true, false><<<gFF1, 256>>>(xn2, w1, b1, nullptr, ffn, MROWS, FF, EMB);

    // 7) FFN2 + residual -> final x (directly into d_out)
    gemm_kernel<false, true><<<gProj, 256>>>(ffn, w2, b2, x1, out, MROWS, EMB, FF);

    // 8) logits + losses
    loss_kernel<<<1, 128>>>(out, wlr, blr, out + X_SIZE);
}